// round 9
// baseline (speedup 1.0000x reference)
#include <cuda_runtime.h>
#include <cstdint>

// Depthwise conv1d, K=7, 'same' padding, softmax over taps.
// x: (B, C, T) fp32; weight: (H, 1, 7); head for channel c is c % H (H=16).
//
// Two kernels overlapped via PDL (programmatic dependent launch):
//   primary  = tiny softmax kernel -> __device__ g_w, then launch_dependents
//   secondary= R2's hot conv kernel (best measured: 75.2us, DRAM 80.7%),
//              launched with programmaticStreamSerialization; it issues its
//              tile LDGs first, then griddepcontrol.wait, then reads g_w.

#define KSIZE 7
#define TILE 2048
#define HALF (TILE / 2)
#define THREADS 256
#define SHIFT 4   // s[SHIFT + i] = x[t0 + i]; halo lives at s[1..3]
#define T_LEN 4096

__device__ float g_w[128];  // softmaxed weights, H*7 used (H=16)

__global__ void softmax_weights_kernel(const float* __restrict__ w, int H) {
    int h = threadIdx.x;
    if (h < H) {
        float v[KSIZE];
        float m = -1e30f;
        #pragma unroll
        for (int k = 0; k < KSIZE; k++) {
            v[k] = w[h * KSIZE + k];
            m = fmaxf(m, v[k]);
        }
        float s = 0.f;
        #pragma unroll
        for (int k = 0; k < KSIZE; k++) s += __expf(v[k] - m);
        float inv = 1.f / s;
        #pragma unroll
        for (int k = 0; k < KSIZE; k++) g_w[h * KSIZE + k] = __expf(v[k] - m) * inv;
    }
    __threadfence();
    asm volatile("griddepcontrol.launch_dependents;" ::: "memory");
}

__global__ __launch_bounds__(THREADS)
void lconv1d_kernel(const float* __restrict__ x, float* __restrict__ out) {
    __shared__ float s[SHIFT + TILE + 3];

    const int row = blockIdx.y;               // b*C + c
    const int t0  = blockIdx.x * TILE;
    const size_t base = (size_t)row * T_LEN + t0;
    const int tid = threadIdx.x;
    const int p0 = tid * 4;
    const int p1 = p0 + HALF;

    // Two independent main-tile loads per thread (MLP=2), aligned STS.128.
    const float4 v0 = *reinterpret_cast<const float4*>(x + base + p0);
    const float4 v1 = *reinterpret_cast<const float4*>(x + base + p1);
    *reinterpret_cast<float4*>(&s[SHIFT + p0]) = v0;
    *reinterpret_cast<float4*>(&s[SHIFT + p1]) = v1;

    // Halos (3 left, 3 right) with zero padding at row boundaries.
    if (tid < 3) {
        s[1 + tid]            = (t0 > 0)            ? x[base - 3 + tid]    : 0.f;
        s[SHIFT + TILE + tid] = (t0 + TILE < T_LEN) ? x[base + TILE + tid] : 0.f;
    }

    // Wait for the softmax primary to publish g_w (tile LDGs already in flight).
    asm volatile("griddepcontrol.wait;" ::: "memory");

    // Weights: warp-uniform loads from precomputed table.
    const int h = row & 15;  // C=1024 is a multiple of H=16
    const float w0 = g_w[h * KSIZE + 0];
    const float w1 = g_w[h * KSIZE + 1];
    const float w2 = g_w[h * KSIZE + 2];
    const float w3 = g_w[h * KSIZE + 3];
    const float w4 = g_w[h * KSIZE + 4];
    const float w5 = g_w[h * KSIZE + 5];
    const float w6 = g_w[h * KSIZE + 6];

    __syncthreads();

    // Chunk 0: outputs [p0 .. p0+3]. Middle float4 == v0 (register reuse).
    {
        const float4 a = *reinterpret_cast<const float4*>(&s[p0]);
        const float4 b = v0;
        const float4 c = *reinterpret_cast<const float4*>(&s[p0 + 8]);
        float4 r;
        r.x = w0*a.y + w1*a.z + w2*a.w + w3*b.x + w4*b.y + w5*b.z + w6*b.w;
        r.y = w0*a.z + w1*a.w + w2*b.x + w3*b.y + w4*b.z + w5*b.w + w6*c.x;
        r.z = w0*a.w + w1*b.x + w2*b.y + w3*b.z + w4*b.w + w5*c.x + w6*c.y;
        r.w = w0*b.x + w1*b.y + w2*b.z + w3*b.w + w4*c.x + w5*c.y + w6*c.z;
        *reinterpret_cast<float4*>(out + base + p0) = r;
    }

    // Chunk 1: outputs [p1 .. p1+3]. Middle float4 == v1.
    {
        const float4 a = *reinterpret_cast<const float4*>(&s[p1]);
        const float4 b = v1;
        const float4 c = *reinterpret_cast<const float4*>(&s[p1 + 8]);
        float4 r;
        r.x = w0*a.y + w1*a.z + w2*a.w + w3*b.x + w4*b.y + w5*b.z + w6*b.w;
        r.y = w0*a.z + w1*a.w + w2*b.x + w3*b.y + w4*b.z + w5*b.w + w6*c.x;
        r.z = w0*a.w + w1*b.x + w2*b.y + w3*b.z + w4*b.w + w5*c.x + w6*c.y;
        r.w = w0*b.x + w1*b.y + w2*b.z + w3*b.w + w4*c.x + w5*c.y + w6*c.z;
        *reinterpret_cast<float4*>(out + base + p1) = r;
    }
}

extern "C" void kernel_launch(void* const* d_in, const int* in_sizes, int n_in,
                              void* d_out, int out_size) {
    const float* x = (const float*)d_in[0];
    const float* w = (const float*)d_in[1];
    float* out = (float*)d_out;

    const int H = in_sizes[1] / KSIZE;      // 16
    const int rows = in_sizes[0] / T_LEN;   // B*C = 16384

    // Primary: tiny softmax kernel.
    softmax_weights_kernel<<<1, 32>>>(w, H);

    // Secondary: conv kernel with programmatic (PDL) overlap.
    cudaLaunchAttribute attrs[1];
    attrs[0].id = cudaLaunchAttributeProgrammaticStreamSerialization;
    attrs[0].val.programmaticStreamSerializationAllowed = 1;

    cudaLaunchConfig_t cfg = {};
    cfg.gridDim  = dim3(T_LEN / TILE, rows);   // (2, 16384)
    cfg.blockDim = dim3(THREADS, 1, 1);
    cfg.dynamicSmemBytes = 0;
    cfg.stream = 0;
    cfg.attrs = attrs;
    cfg.numAttrs = 1;

    cudaLaunchKernelEx(&cfg, lconv1d_kernel, x, out);
}